// round 3
// baseline (speedup 1.0000x reference)
#include <cuda_runtime.h>
#include <cstdint>

#define DSZ 64
#define N_SRC 50000
#define N_ALL 100000
#define E_ALL 1600000
#define TILE_E 8
#define TPB 128

// scratch for per-node transform y1[v] = W1 x[v] + (b1+b2)
__device__ __align__(16) float g_y1[(size_t)N_ALL * DSZ];

__device__ __forceinline__ float load_x(const float* __restrict__ se,
                                        const float* __restrict__ de,
                                        int v, int d) {
    return (v < N_SRC) ? se[(size_t)v * DSZ + d]
                       : de[(size_t)(v - N_SRC) * DSZ + d];
}

// ---------------- node transform: y1 = X @ W1^T + (b1+b2) ----------------
__global__ void node_transform_kernel(const float* __restrict__ src_emb,
                                      const float* __restrict__ dst_emb,
                                      const float* __restrict__ W1,
                                      const float* __restrict__ b1,
                                      const float* __restrict__ b2) {
    __shared__ __align__(16) float W1T[DSZ * DSZ];   // W1T[d*64+o] = W1[o*64+d]
    __shared__ __align__(16) float bias[DSZ];
    __shared__ float xs[TILE_E][DSZ + 1];            // pad -> no bank conflicts

    const int tid = threadIdx.x;
    for (int i = tid; i < DSZ * DSZ; i += TPB) {
        int o = i >> 6, d = i & 63;
        W1T[d * DSZ + o] = W1[i];
    }
    if (tid < DSZ) bias[tid] = b1[tid] + b2[tid];
    __syncthreads();

    const int ntiles = N_ALL / TILE_E;   // 12500 exactly
    for (int tile = blockIdx.x; tile < ntiles; tile += gridDim.x) {
        const int base = tile * TILE_E;
        for (int i = tid; i < TILE_E * DSZ; i += TPB) {
            int r = i >> 6, d = i & 63;
            xs[r][d] = load_x(src_emb, dst_emb, base + r, d);
        }
        __syncthreads();

        const int e = tid >> 4;       // node within tile 0..7
        const int q = tid & 15;       // output quad 0..15
        float4 acc = make_float4(0.f, 0.f, 0.f, 0.f);
        #pragma unroll
        for (int d = 0; d < DSZ; d++) {
            float pv = xs[e][d];
            float4 w = *(const float4*)&W1T[d * DSZ + 4 * q];
            acc.x = fmaf(pv, w.x, acc.x);
            acc.y = fmaf(pv, w.y, acc.y);
            acc.z = fmaf(pv, w.z, acc.z);
            acc.w = fmaf(pv, w.w, acc.w);
        }
        float4 b4 = *(const float4*)&bias[4 * q];
        acc.x += b4.x; acc.y += b4.y; acc.z += b4.z; acc.w += b4.w;
        *(float4*)&g_y1[(size_t)(base + e) * DSZ + 4 * q] = acc;
        __syncthreads();
    }
}

// ---------------- per-edge: scatter norm*(y1[src] + W2 (xs*xd)) ----------------
__global__ void edge_kernel(const float* __restrict__ src_emb,
                            const float* __restrict__ dst_emb,
                            const float* __restrict__ norm,
                            const float* __restrict__ W2,
                            const int* __restrict__ esrc,
                            const int* __restrict__ edst,
                            float* __restrict__ out) {
    __shared__ __align__(16) float W2T[DSZ * DSZ];
    __shared__ float p[TILE_E][DSZ + 1];
    __shared__ int s_src[TILE_E];
    __shared__ int s_dst[TILE_E];
    __shared__ float s_norm[TILE_E];

    const int tid = threadIdx.x;
    for (int i = tid; i < DSZ * DSZ; i += TPB) {
        int o = i >> 6, d = i & 63;
        W2T[d * DSZ + o] = W2[i];
    }
    __syncthreads();

    const int ntiles = E_ALL / TILE_E;   // 200000 exactly
    for (int tile = blockIdx.x; tile < ntiles; tile += gridDim.x) {
        const int ebase = tile * TILE_E;
        if (tid < TILE_E) {
            s_src[tid]  = esrc[ebase + tid];
            s_dst[tid]  = edst[ebase + tid];
            s_norm[tid] = norm[ebase + tid];
        }
        __syncthreads();

        // phase A: gather xs, xd and form elementwise product
        for (int i = tid; i < TILE_E * DSZ; i += TPB) {
            int r = i >> 6, d = i & 63;
            int s = s_src[r], t = s_dst[r];
            float a = load_x(src_emb, dst_emb, s, d);
            float b = load_x(src_emb, dst_emb, t, d);
            p[r][d] = a * b;
        }
        __syncthreads();

        // phase B: y2 = W2 * p, add gathered y1[src], scale, vector-red scatter
        const int e = tid >> 4;
        const int q = tid & 15;
        float4 acc = make_float4(0.f, 0.f, 0.f, 0.f);
        #pragma unroll
        for (int d = 0; d < DSZ; d++) {
            float pv = p[e][d];
            float4 w = *(const float4*)&W2T[d * DSZ + 4 * q];
            acc.x = fmaf(pv, w.x, acc.x);
            acc.y = fmaf(pv, w.y, acc.y);
            acc.z = fmaf(pv, w.z, acc.z);
            acc.w = fmaf(pv, w.w, acc.w);
        }
        const int   s  = s_src[e];
        const float nv = s_norm[e];
        float4 y = *(const float4*)&g_y1[(size_t)s * DSZ + 4 * q];
        float4 m;
        m.x = nv * (acc.x + y.x);
        m.y = nv * (acc.y + y.y);
        m.z = nv * (acc.z + y.z);
        m.w = nv * (acc.w + y.w);

        uintptr_t addr = (uintptr_t)&out[(size_t)s_dst[e] * DSZ + 4 * q];
        asm volatile("red.global.add.v4.f32 [%0], {%1, %2, %3, %4};"
                     :: "l"(addr), "f"(m.x), "f"(m.y), "f"(m.z), "f"(m.w)
                     : "memory");
        __syncthreads();
    }
}

// ---------------- epilogue: LeakyReLU(0.2) in place ----------------
__global__ void lrelu_kernel(float* __restrict__ out, int n4) {
    int i = blockIdx.x * blockDim.x + threadIdx.x;
    if (i < n4) {
        float4 v = ((float4*)out)[i];
        v.x = v.x > 0.f ? v.x : 0.2f * v.x;
        v.y = v.y > 0.f ? v.y : 0.2f * v.y;
        v.z = v.z > 0.f ? v.z : 0.2f * v.z;
        v.w = v.w > 0.f ? v.w : 0.2f * v.w;
        ((float4*)out)[i] = v;
    }
}

extern "C" void kernel_launch(void* const* d_in, const int* in_sizes, int n_in,
                              void* d_out, int out_size) {
    const float* src_emb = (const float*)d_in[0];
    const float* dst_emb = (const float*)d_in[1];
    const float* norm    = (const float*)d_in[2];
    const float* W1      = (const float*)d_in[3];
    const float* b1      = (const float*)d_in[4];
    const float* W2      = (const float*)d_in[5];
    const float* b2      = (const float*)d_in[6];
    const int*   esrc    = (const int*)d_in[7];
    const int*   edst    = (const int*)d_in[8];
    float* out = (float*)d_out;

    // output accumulates scatter-sums: zero it first
    cudaMemsetAsync(d_out, 0, (size_t)out_size * sizeof(float));

    node_transform_kernel<<<4736, TPB>>>(src_emb, dst_emb, W1, b1, b2);
    edge_kernel<<<4736, TPB>>>(src_emb, dst_emb, norm, W2, esrc, edst, out);

    int n4 = out_size / 4;
    lrelu_kernel<<<(n4 + 255) / 256, 256>>>(out, n4);
}

// round 4
// speedup vs baseline: 1.8209x; 1.8209x over previous
#include <cuda_runtime.h>
#include <cstdint>

#define DSZ 64
#define N_SRC 50000
#define N_ALL 100000
#define E_ALL 1600000
#define TPB 128
#define ETILE 32
#define PSTR 34   // padded row stride (floats) for transposed tile; even -> 8B aligned pairs

typedef unsigned long long f32x2_t;

__device__ __align__(16) float g_y1[(size_t)N_ALL * DSZ];

__device__ __forceinline__ f32x2_t ffma2(f32x2_t a, f32x2_t b, f32x2_t c) {
    f32x2_t d;
    asm("fma.rn.f32x2 %0, %1, %2, %3;" : "=l"(d) : "l"(a), "l"(b), "l"(c));
    return d;
}
__device__ __forceinline__ f32x2_t dup2(float x) {
    f32x2_t d; unsigned u = __float_as_uint(x);
    asm("mov.b64 %0, {%1, %1};" : "=l"(d) : "r"(u));
    return d;
}
__device__ __forceinline__ void unpack2(f32x2_t v, float& lo, float& hi) {
    unsigned a, b;
    asm("mov.b64 {%0, %1}, %2;" : "=r"(a), "=r"(b) : "l"(v));
    lo = __uint_as_float(a); hi = __uint_as_float(b);
}

__device__ __forceinline__ float4 ldx4(const float* __restrict__ se,
                                       const float* __restrict__ de,
                                       int v, int q) {
    const float* p = (v < N_SRC) ? se + (size_t)v * DSZ
                                 : de + (size_t)(v - N_SRC) * DSZ;
    return *(const float4*)(p + 4 * q);
}

// ================= node transform: y1 = X @ W1^T + (b1+b2) =================
__global__ void node_transform_kernel(const float* __restrict__ src_emb,
                                      const float* __restrict__ dst_emb,
                                      const float* __restrict__ W1,
                                      const float* __restrict__ b1,
                                      const float* __restrict__ b2) {
    __shared__ __align__(16) float WT[DSZ * DSZ];     // WT[d*64+o] = W1[o*64+d]
    __shared__ __align__(16) float xt[DSZ * PSTR];    // xt[d*PSTR+e]

    const int tid = threadIdx.x;
    for (int i = tid; i < DSZ * DSZ; i += TPB) {
        int o = i >> 6, d = i & 63;
        WT[d * DSZ + o] = W1[i];
    }
    __syncthreads();

    const int lane = tid & 31;
    const int w    = tid >> 5;
    const int q16  = lane & 15;           // output quad for phase B
    const int eg   = lane >> 4;           // 0/1
    const int e_base = w * 8 + eg * 4;    // 4 nodes per thread

    const int ntiles = N_ALL / ETILE;     // 3125
    for (int tile = blockIdx.x; tile < ntiles; tile += gridDim.x) {
        const int base = tile * ETILE;

        // phase A: stage x transposed (conflict-free STS: lane == e)
        {
            const int e = tid & 31;
            const int v = base + e;
            #pragma unroll
            for (int j = 0; j < 4; j++) {
                int q = j * 4 + (tid >> 5);
                float4 a = ldx4(src_emb, dst_emb, v, q);
                xt[(4 * q + 0) * PSTR + e] = a.x;
                xt[(4 * q + 1) * PSTR + e] = a.y;
                xt[(4 * q + 2) * PSTR + e] = a.z;
                xt[(4 * q + 3) * PSTR + e] = a.w;
            }
        }
        __syncthreads();

        // phase B: 4 outputs x 4 nodes per thread, FFMA2 packed over node pairs
        f32x2_t a00 = 0, a01 = 0, a10 = 0, a11 = 0,
                a20 = 0, a21 = 0, a30 = 0, a31 = 0;
        #pragma unroll 4
        for (int d = 0; d < DSZ; d++) {
            float4 wv = *(const float4*)&WT[d * DSZ + 4 * q16];
            f32x2_t p01 = *(const f32x2_t*)&xt[d * PSTR + e_base];
            f32x2_t p23 = *(const f32x2_t*)&xt[d * PSTR + e_base + 2];
            f32x2_t wx = dup2(wv.x), wy = dup2(wv.y), wz = dup2(wv.z), ww = dup2(wv.w);
            a00 = ffma2(p01, wx, a00); a01 = ffma2(p23, wx, a01);
            a10 = ffma2(p01, wy, a10); a11 = ffma2(p23, wy, a11);
            a20 = ffma2(p01, wz, a20); a21 = ffma2(p23, wz, a21);
            a30 = ffma2(p01, ww, a30); a31 = ffma2(p23, ww, a31);
        }
        float v0[4], v1[4], v2[4], v3[4];
        unpack2(a00, v0[0], v0[1]); unpack2(a01, v0[2], v0[3]);
        unpack2(a10, v1[0], v1[1]); unpack2(a11, v1[2], v1[3]);
        unpack2(a20, v2[0], v2[1]); unpack2(a21, v2[2], v2[3]);
        unpack2(a30, v3[0], v3[1]); unpack2(a31, v3[2], v3[3]);

        float4 bias;
        bias.x = b1[4 * q16 + 0] + b2[4 * q16 + 0];
        bias.y = b1[4 * q16 + 1] + b2[4 * q16 + 1];
        bias.z = b1[4 * q16 + 2] + b2[4 * q16 + 2];
        bias.w = b1[4 * q16 + 3] + b2[4 * q16 + 3];

        #pragma unroll
        for (int k = 0; k < 4; k++) {
            float4 r;
            r.x = v0[k] + bias.x; r.y = v1[k] + bias.y;
            r.z = v2[k] + bias.z; r.w = v3[k] + bias.w;
            *(float4*)&g_y1[(size_t)(base + e_base + k) * DSZ + 4 * q16] = r;
        }
        __syncthreads();
    }
}

// ============ edge kernel: scatter norm*(y1[src] + W2 (xs*xd)) ============
__global__ void edge_kernel(const float* __restrict__ src_emb,
                            const float* __restrict__ dst_emb,
                            const float* __restrict__ norm,
                            const float* __restrict__ W2,
                            const int* __restrict__ esrc,
                            const int* __restrict__ edst,
                            float* __restrict__ out) {
    __shared__ __align__(16) float WT[DSZ * DSZ];     // WT[d*64+o] = W2[o*64+d]
    __shared__ __align__(16) float pt[DSZ * PSTR];    // pt[d*PSTR+e] = xs[d]*xd[d]

    const int tid = threadIdx.x;
    for (int i = tid; i < DSZ * DSZ; i += TPB) {
        int o = i >> 6, d = i & 63;
        WT[d * DSZ + o] = W2[i];
    }
    __syncthreads();

    const int lane = tid & 31;
    const int w    = tid >> 5;
    const int q16  = lane & 15;
    const int eg   = lane >> 4;
    const int e_base = w * 8 + eg * 4;    // 4 edges per thread in phase B

    const int ntiles = E_ALL / ETILE;     // 50000
    for (int tile = blockIdx.x; tile < ntiles; tile += gridDim.x) {
        const int ebase = tile * ETILE;

        // phase A: gather + elementwise product, staged transposed
        {
            const int e = tid & 31;
            const int s = esrc[ebase + e];
            const int t = edst[ebase + e];
            #pragma unroll
            for (int j = 0; j < 4; j++) {
                int q = j * 4 + (tid >> 5);
                float4 a = ldx4(src_emb, dst_emb, s, q);
                float4 b = ldx4(src_emb, dst_emb, t, q);
                pt[(4 * q + 0) * PSTR + e] = a.x * b.x;
                pt[(4 * q + 1) * PSTR + e] = a.y * b.y;
                pt[(4 * q + 2) * PSTR + e] = a.z * b.z;
                pt[(4 * q + 3) * PSTR + e] = a.w * b.w;
            }
        }
        __syncthreads();

        // phase B: y2 = W2 * p for 4 edges x 4 outputs per thread (FFMA2)
        f32x2_t a00 = 0, a01 = 0, a10 = 0, a11 = 0,
                a20 = 0, a21 = 0, a30 = 0, a31 = 0;
        #pragma unroll 4
        for (int d = 0; d < DSZ; d++) {
            float4 wv = *(const float4*)&WT[d * DSZ + 4 * q16];
            f32x2_t p01 = *(const f32x2_t*)&pt[d * PSTR + e_base];
            f32x2_t p23 = *(const f32x2_t*)&pt[d * PSTR + e_base + 2];
            f32x2_t wx = dup2(wv.x), wy = dup2(wv.y), wz = dup2(wv.z), ww = dup2(wv.w);
            a00 = ffma2(p01, wx, a00); a01 = ffma2(p23, wx, a01);
            a10 = ffma2(p01, wy, a10); a11 = ffma2(p23, wy, a11);
            a20 = ffma2(p01, wz, a20); a21 = ffma2(p23, wz, a21);
            a30 = ffma2(p01, ww, a30); a31 = ffma2(p23, ww, a31);
        }
        float v0[4], v1[4], v2[4], v3[4];
        unpack2(a00, v0[0], v0[1]); unpack2(a01, v0[2], v0[3]);
        unpack2(a10, v1[0], v1[1]); unpack2(a11, v1[2], v1[3]);
        unpack2(a20, v2[0], v2[1]); unpack2(a21, v2[2], v2[3]);
        unpack2(a30, v3[0], v3[1]); unpack2(a31, v3[2], v3[3]);

        #pragma unroll
        for (int k = 0; k < 4; k++) {
            const int ei = ebase + e_base + k;
            const int s  = esrc[ei];
            const float nv = norm[ei];
            float4 y = *(const float4*)&g_y1[(size_t)s * DSZ + 4 * q16];
            float mx = nv * (v0[k] + y.x);
            float my = nv * (v1[k] + y.y);
            float mz = nv * (v2[k] + y.z);
            float mw = nv * (v3[k] + y.w);
            uintptr_t addr = (uintptr_t)&out[(size_t)edst[ei] * DSZ + 4 * q16];
            asm volatile("red.global.add.v4.f32 [%0], {%1, %2, %3, %4};"
                         :: "l"(addr), "f"(mx), "f"(my), "f"(mz), "f"(mw)
                         : "memory");
        }
        __syncthreads();
    }
}

// ================= epilogue: LeakyReLU(0.2) in place =================
__global__ void lrelu_kernel(float* __restrict__ out, int n4) {
    int i = blockIdx.x * blockDim.x + threadIdx.x;
    if (i < n4) {
        float4 v = ((float4*)out)[i];
        v.x = v.x > 0.f ? v.x : 0.2f * v.x;
        v.y = v.y > 0.f ? v.y : 0.2f * v.y;
        v.z = v.z > 0.f ? v.z : 0.2f * v.z;
        v.w = v.w > 0.f ? v.w : 0.2f * v.w;
        ((float4*)out)[i] = v;
    }
}

extern "C" void kernel_launch(void* const* d_in, const int* in_sizes, int n_in,
                              void* d_out, int out_size) {
    const float* src_emb = (const float*)d_in[0];
    const float* dst_emb = (const float*)d_in[1];
    const float* norm    = (const float*)d_in[2];
    const float* W1      = (const float*)d_in[3];
    const float* b1      = (const float*)d_in[4];
    const float* W2      = (const float*)d_in[5];
    const float* b2      = (const float*)d_in[6];
    const int*   esrc    = (const int*)d_in[7];
    const int*   edst    = (const int*)d_in[8];
    float* out = (float*)d_out;

    cudaMemsetAsync(d_out, 0, (size_t)out_size * sizeof(float));

    node_transform_kernel<<<1184, TPB>>>(src_emb, dst_emb, W1, b1, b2);
    edge_kernel<<<4736, TPB>>>(src_emb, dst_emb, norm, W2, esrc, edst, out);

    int n4 = out_size / 4;
    lrelu_kernel<<<(n4 + 255) / 256, 256>>>(out, n4);
}